// round 1
// baseline (speedup 1.0000x reference)
#include <cuda_runtime.h>
#include <math.h>

#define BATCH 8
#define SEQ   2048
#define DIM   512
#define SH    128
#define EXP   1024
#define PROJ  2176            // 2*EXP + SH
#define NROWS (BATCH * SEQ)   // 16384

// -------------------- scratch (no allocations allowed) --------------------
__device__ float g_xn [NROWS * DIM];                 //  33.5 MB  rmsnormed x
__device__ float g_uv [(size_t)NROWS * PROJ];        // 142.6 MB  swish(xn@W1+b1)
__device__ float g_q  [NROWS * SH];                  //   8.4 MB
__device__ float g_k  [NROWS * SH];                  //   8.4 MB
__device__ float g_att[(size_t)BATCH * SEQ * SEQ];   // 134.2 MB  relu(qk)^2
__device__ float g_o  [(size_t)NROWS * EXP];         //  67.1 MB  u * (att @ v)
__device__ float g_f  [2 * SEQ - 1];                 // toeplitz rope bias f(m-n)

// -------------------- rmsnorm --------------------
__global__ void rmsnorm_kernel(const float* __restrict__ x,
                               const float* __restrict__ ns_p) {
    int row = blockIdx.x;
    const float* xr = x + (size_t)row * DIM;
    float* outr = g_xn + (size_t)row * DIM;
    float s = 0.f;
    for (int i = threadIdx.x; i < DIM; i += blockDim.x) {
        float v = xr[i];
        s += v * v;
    }
    __shared__ float warp_s[4];
    #pragma unroll
    for (int off = 16; off > 0; off >>= 1) s += __shfl_down_sync(0xffffffffu, s, off);
    int lane = threadIdx.x & 31, wid = threadIdx.x >> 5;
    if (lane == 0) warp_s[wid] = s;
    __syncthreads();
    if (wid == 0) {
        float t = (lane < 4) ? warp_s[lane] : 0.f;
        #pragma unroll
        for (int off = 2; off > 0; off >>= 1) t += __shfl_down_sync(0xffffffffu, t, off);
        if (lane == 0) warp_s[0] = t;
    }
    __syncthreads();
    float scale = rsqrtf(warp_s[0] * (1.f / (float)DIM) + 1e-6f) * ns_p[0];
    for (int i = threadIdx.x; i < DIM; i += blockDim.x) outr[i] = xr[i] * scale;
}

// -------------------- toeplitz rope bias: f(d) --------------------
// T[m,n] = ar[m].br[n] = sum_i p_i*cos((m-n)*th_i) - r_i*sin((m-n)*th_i)
// p_i = a1*b1 + a2*b2 ; r_i = a2*b1 - a1*b2 ; th_i = 10000^{-i/(SEQ/2)}
__global__ void toeplitz_kernel(const float* __restrict__ a,
                                const float* __restrict__ b) {
    __shared__ float sp[SEQ / 2];
    __shared__ float sr[SEQ / 2];
    for (int i = threadIdx.x; i < SEQ / 2; i += blockDim.x) {
        float a1 = a[i], a2 = a[i + SEQ / 2];
        float b1v = b[i], b2v = b[i + SEQ / 2];
        sp[i] = a1 * b1v + a2 * b2v;
        sr[i] = a2 * b1v - a1 * b2v;
    }
    __syncthreads();
    int d = blockIdx.x * blockDim.x + threadIdx.x;   // d in [0, SEQ-1]
    if (d >= SEQ) return;
    float sumc = 0.f, sums = 0.f;
    const float log1e4 = 9.210340371976184f;         // ln(10000)
    for (int i = 0; i < SEQ / 2; i++) {
        float theta = expf(-((float)i * (1.f / (SEQ / 2))) * log1e4);
        float s, c;
        sincosf((float)d * theta, &s, &c);
        sumc += sp[i] * c;
        sums += sr[i] * s;
    }
    g_f[(SEQ - 1) + d] = sumc - sums;   // f(+d)
    g_f[(SEQ - 1) - d] = sumc + sums;   // f(-d)
}

// -------------------- GEMM1: uv = swish(xn @ W1 + b1) --------------------
// M=NROWS, N=PROJ, K=DIM
__global__ void gemm1_kernel(const float* __restrict__ W1,
                             const float* __restrict__ b1) {
    __shared__ float As[16][64];
    __shared__ float Bs[16][64];
    int tid = threadIdx.x;
    int tx = tid & 15, ty = tid >> 4;
    int bm = blockIdx.y * 64, bn = blockIdx.x * 64;
    float acc[4][4] = {};
    for (int k0 = 0; k0 < DIM; k0 += 16) {
        #pragma unroll
        for (int l = 0; l < 4; l++) {
            int i = tid + l * 256;
            As[i & 15][i >> 4] = g_xn[(size_t)(bm + (i >> 4)) * DIM + (k0 + (i & 15))];
            Bs[i >> 6][i & 63] = W1[(size_t)(k0 + (i >> 6)) * PROJ + (bn + (i & 63))];
        }
        __syncthreads();
        #pragma unroll
        for (int kk = 0; kk < 16; kk++) {
            float av[4], bv[4];
            #pragma unroll
            for (int i = 0; i < 4; i++) av[i] = As[kk][ty * 4 + i];
            #pragma unroll
            for (int j = 0; j < 4; j++) bv[j] = Bs[kk][tx * 4 + j];
            #pragma unroll
            for (int i = 0; i < 4; i++)
                #pragma unroll
                for (int j = 0; j < 4; j++) acc[i][j] += av[i] * bv[j];
        }
        __syncthreads();
    }
    #pragma unroll
    for (int i = 0; i < 4; i++) {
        int m = bm + ty * 4 + i;
        #pragma unroll
        for (int j = 0; j < 4; j++) {
            int n = bn + tx * 4 + j;
            float c = acc[i][j] + b1[n];
            g_uv[(size_t)m * PROJ + n] = c / (1.f + expf(-c));   // swish
        }
    }
}

// -------------------- q,k from base --------------------
__global__ void qkgen_kernel(const float* __restrict__ gamma,
                             const float* __restrict__ beta) {
    int idx = blockIdx.x * blockDim.x + threadIdx.x;   // NROWS*SH threads
    int j = idx & (SH - 1);
    int row = idx >> 7;
    float base = g_uv[(size_t)row * PROJ + 2 * EXP + j];
    g_q[idx] = base * gamma[j]      + beta[j];
    g_k[idx] = base * gamma[SH + j] + beta[SH + j];
}

// -------------------- attn: att = relu(q@k^T/SEQ + f(m-n))^2 --------------------
// per batch: M=N=SEQ, K=SH (NT gemm)
__global__ void attn_kernel() {
    __shared__ float As[16][64];
    __shared__ float Bs[16][64];
    int tid = threadIdx.x;
    int tx = tid & 15, ty = tid >> 4;
    int bz = blockIdx.z;
    int bm = blockIdx.y * 64, bn = blockIdx.x * 64;
    const float* Q  = g_q + (size_t)bz * SEQ * SH;
    const float* Kp = g_k + (size_t)bz * SEQ * SH;
    float acc[4][4] = {};
    for (int k0 = 0; k0 < SH; k0 += 16) {
        #pragma unroll
        for (int l = 0; l < 4; l++) {
            int i = tid + l * 256;
            int r = i >> 4, kk = i & 15;
            As[kk][r] = Q [(size_t)(bm + r) * SH + (k0 + kk)];
            Bs[kk][r] = Kp[(size_t)(bn + r) * SH + (k0 + kk)];
        }
        __syncthreads();
        #pragma unroll
        for (int kk = 0; kk < 16; kk++) {
            float av[4], bv[4];
            #pragma unroll
            for (int i = 0; i < 4; i++) av[i] = As[kk][ty * 4 + i];
            #pragma unroll
            for (int j = 0; j < 4; j++) bv[j] = Bs[kk][tx * 4 + j];
            #pragma unroll
            for (int i = 0; i < 4; i++)
                #pragma unroll
                for (int j = 0; j < 4; j++) acc[i][j] += av[i] * bv[j];
        }
        __syncthreads();
    }
    float* att = g_att + (size_t)bz * SEQ * SEQ;
    #pragma unroll
    for (int i = 0; i < 4; i++) {
        int m = bm + ty * 4 + i;
        #pragma unroll
        for (int j = 0; j < 4; j++) {
            int n = bn + tx * 4 + j;
            float c = acc[i][j] * (1.f / (float)SEQ) + g_f[m - n + (SEQ - 1)];
            c = fmaxf(c, 0.f);
            att[(size_t)m * SEQ + n] = c * c;
        }
    }
}

// -------------------- o = u * (att @ v) --------------------
// per batch: M=SEQ, N=EXP, K=SEQ ; v = uv[:, EXP:2*EXP], u = uv[:, :EXP]
__global__ void o_kernel() {
    __shared__ float As[16][64];
    __shared__ float Bs[16][64];
    int tid = threadIdx.x;
    int tx = tid & 15, ty = tid >> 4;
    int bz = blockIdx.z;
    int bm = blockIdx.y * 64, bn = blockIdx.x * 64;
    const float* A = g_att + (size_t)bz * SEQ * SEQ;
    const float* V = g_uv + (size_t)bz * SEQ * PROJ + EXP;   // ld = PROJ
    float acc[4][4] = {};
    for (int k0 = 0; k0 < SEQ; k0 += 16) {
        #pragma unroll
        for (int l = 0; l < 4; l++) {
            int i = tid + l * 256;
            As[i & 15][i >> 4] = A[(size_t)(bm + (i >> 4)) * SEQ + (k0 + (i & 15))];
            Bs[i >> 6][i & 63] = V[(size_t)(k0 + (i >> 6)) * PROJ + (bn + (i & 63))];
        }
        __syncthreads();
        #pragma unroll
        for (int kk = 0; kk < 16; kk++) {
            float av[4], bv[4];
            #pragma unroll
            for (int i = 0; i < 4; i++) av[i] = As[kk][ty * 4 + i];
            #pragma unroll
            for (int j = 0; j < 4; j++) bv[j] = Bs[kk][tx * 4 + j];
            #pragma unroll
            for (int i = 0; i < 4; i++)
                #pragma unroll
                for (int j = 0; j < 4; j++) acc[i][j] += av[i] * bv[j];
        }
        __syncthreads();
    }
    #pragma unroll
    for (int i = 0; i < 4; i++) {
        int m = bm + ty * 4 + i;
        #pragma unroll
        for (int j = 0; j < 4; j++) {
            int n = bn + tx * 4 + j;
            float u = g_uv[(size_t)(bz * SEQ + m) * PROJ + n];
            g_o[(size_t)(bz * SEQ + m) * EXP + n] = acc[i][j] * u;
        }
    }
}

// -------------------- out = o @ W2 + b2 + x --------------------
// M=NROWS, N=DIM, K=EXP
__global__ void out_kernel(const float* __restrict__ W2,
                           const float* __restrict__ b2,
                           const float* __restrict__ x,
                           float* __restrict__ out) {
    __shared__ float As[16][64];
    __shared__ float Bs[16][64];
    int tid = threadIdx.x;
    int tx = tid & 15, ty = tid >> 4;
    int bm = blockIdx.y * 64, bn = blockIdx.x * 64;
    float acc[4][4] = {};
    for (int k0 = 0; k0 < EXP; k0 += 16) {
        #pragma unroll
        for (int l = 0; l < 4; l++) {
            int i = tid + l * 256;
            As[i & 15][i >> 4] = g_o[(size_t)(bm + (i >> 4)) * EXP + (k0 + (i & 15))];
            Bs[i >> 6][i & 63] = W2[(size_t)(k0 + (i >> 6)) * DIM + (bn + (i & 63))];
        }
        __syncthreads();
        #pragma unroll
        for (int kk = 0; kk < 16; kk++) {
            float av[4], bv[4];
            #pragma unroll
            for (int i = 0; i < 4; i++) av[i] = As[kk][ty * 4 + i];
            #pragma unroll
            for (int j = 0; j < 4; j++) bv[j] = Bs[kk][tx * 4 + j];
            #pragma unroll
            for (int i = 0; i < 4; i++)
                #pragma unroll
                for (int j = 0; j < 4; j++) acc[i][j] += av[i] * bv[j];
        }
        __syncthreads();
    }
    #pragma unroll
    for (int i = 0; i < 4; i++) {
        int m = bm + ty * 4 + i;
        #pragma unroll
        for (int j = 0; j < 4; j++) {
            int n = bn + tx * 4 + j;
            out[(size_t)m * DIM + n] = acc[i][j] + b2[n] + x[(size_t)m * DIM + n];
        }
    }
}

// -------------------- launch --------------------
extern "C" void kernel_launch(void* const* d_in, const int* in_sizes, int n_in,
                              void* d_out, int out_size) {
    const float* x          = (const float*)d_in[0];
    const float* W1         = (const float*)d_in[1];
    const float* b1         = (const float*)d_in[2];
    const float* W2         = (const float*)d_in[3];
    const float* b2         = (const float*)d_in[4];
    const float* rope_a     = (const float*)d_in[5];
    const float* rope_b     = (const float*)d_in[6];
    const float* gamma      = (const float*)d_in[7];
    const float* beta       = (const float*)d_in[8];
    const float* norm_scale = (const float*)d_in[9];
    float* out = (float*)d_out;

    rmsnorm_kernel <<<NROWS, 128>>>(x, norm_scale);
    toeplitz_kernel<<<SEQ / 256, 256>>>(rope_a, rope_b);
    gemm1_kernel   <<<dim3(PROJ / 64, NROWS / 64), 256>>>(W1, b1);
    qkgen_kernel   <<<NROWS * SH / 256, 256>>>(gamma, beta);
    attn_kernel    <<<dim3(SEQ / 64, SEQ / 64, BATCH), 256>>>();
    o_kernel       <<<dim3(EXP / 64, SEQ / 64, BATCH), 256>>>();
    out_kernel     <<<dim3(DIM / 64, NROWS / 64), 256>>>(W2, b2, x, out);
}

// round 2
// speedup vs baseline: 6.8103x; 6.8103x over previous
#include <cuda_runtime.h>
#include <cuda_bf16.h>
#include <math.h>
#include <stdint.h>

#define BATCH 8
#define SEQ   2048
#define DIM   512
#define SH    128
#define EXP   1024
#define PROJ  2176            // 2*EXP + SH
#define NROWS (BATCH * SEQ)   // 16384

#define BM 128
#define BN 128
#define BK 32
#define LDSH 40               // BK + 8 halves per smem row (80B, 16B aligned)

// -------------------- scratch (no allocations allowed) --------------------
__device__ alignas(16) __nv_bfloat16 g_xnb[NROWS * DIM];
__device__ alignas(16) __nv_bfloat16 g_uvb[(size_t)NROWS * PROJ];
__device__ alignas(16) __nv_bfloat16 g_w1t[(size_t)PROJ * DIM];     // W1^T
__device__ alignas(16) __nv_bfloat16 g_w2t[(size_t)DIM * EXP];      // W2^T
__device__ alignas(16) __nv_bfloat16 g_qb [NROWS * SH];
__device__ alignas(16) __nv_bfloat16 g_kb [NROWS * SH];
__device__ alignas(16) __nv_bfloat16 g_attb[(size_t)BATCH * SEQ * SEQ];
__device__ alignas(16) __nv_bfloat16 g_vtb [(size_t)BATCH * EXP * SEQ]; // v^T per batch
__device__ alignas(16) __nv_bfloat16 g_ob  [(size_t)NROWS * EXP];
__device__ float g_f[2 * SEQ - 1];

// -------------------- helpers --------------------
__device__ __forceinline__ void cp16(void* smem, const void* gmem) {
    uint32_t s = (uint32_t)__cvta_generic_to_shared(smem);
    asm volatile("cp.async.ca.shared.global [%0], [%1], 16;\n" :: "r"(s), "l"(gmem));
}
__device__ __forceinline__ void mma16816(float* c, const uint32_t* a, const uint32_t* b) {
    asm volatile(
        "mma.sync.aligned.m16n8k16.row.col.f32.bf16.bf16.f32 "
        "{%0,%1,%2,%3},{%4,%5,%6,%7},{%8,%9},{%0,%1,%2,%3};\n"
        : "+f"(c[0]), "+f"(c[1]), "+f"(c[2]), "+f"(c[3])
        : "r"(a[0]), "r"(a[1]), "r"(a[2]), "r"(a[3]), "r"(b[0]), "r"(b[1]));
}

// -------------------- rmsnorm -> bf16 --------------------
__global__ void rmsnorm_kernel(const float* __restrict__ x,
                               const float* __restrict__ ns_p) {
    int row = blockIdx.x;
    const float* xr = x + (size_t)row * DIM;
    __nv_bfloat16* outr = g_xnb + (size_t)row * DIM;
    float s = 0.f;
    for (int i = threadIdx.x; i < DIM; i += blockDim.x) {
        float v = xr[i];
        s += v * v;
    }
    __shared__ float warp_s[4];
    #pragma unroll
    for (int off = 16; off > 0; off >>= 1) s += __shfl_down_sync(0xffffffffu, s, off);
    int lane = threadIdx.x & 31, wid = threadIdx.x >> 5;
    if (lane == 0) warp_s[wid] = s;
    __syncthreads();
    if (wid == 0) {
        float t = (lane < 4) ? warp_s[lane] : 0.f;
        #pragma unroll
        for (int off = 2; off > 0; off >>= 1) t += __shfl_down_sync(0xffffffffu, t, off);
        if (lane == 0) warp_s[0] = t;
    }
    __syncthreads();
    float scale = rsqrtf(warp_s[0] * (1.f / (float)DIM) + 1e-6f) * ns_p[0];
    for (int i = threadIdx.x; i < DIM; i += blockDim.x)
        outr[i] = __float2bfloat16(xr[i] * scale);
}

// -------------------- toeplitz rope bias: f(d) --------------------
__global__ void toeplitz_kernel(const float* __restrict__ a,
                                const float* __restrict__ b) {
    __shared__ float sp[SEQ / 2];
    __shared__ float sr[SEQ / 2];
    for (int i = threadIdx.x; i < SEQ / 2; i += blockDim.x) {
        float a1 = a[i], a2 = a[i + SEQ / 2];
        float b1v = b[i], b2v = b[i + SEQ / 2];
        sp[i] = a1 * b1v + a2 * b2v;
        sr[i] = a2 * b1v - a1 * b2v;
    }
    __syncthreads();
    int d = blockIdx.x * blockDim.x + threadIdx.x;
    if (d >= SEQ) return;
    float sumc = 0.f, sums = 0.f;
    const float log1e4 = 9.210340371976184f;
    for (int i = 0; i < SEQ / 2; i++) {
        float theta = expf(-((float)i * (1.f / (SEQ / 2))) * log1e4);
        float s, c;
        sincosf((float)d * theta, &s, &c);
        sumc += sp[i] * c;
        sums += sr[i] * s;
    }
    g_f[(SEQ - 1) + d] = sumc - sums;
    g_f[(SEQ - 1) - d] = sumc + sums;
}

// -------------------- weight transpose fp32 -> bf16 --------------------
// out[c][r] = in[r][c] ; out dims cols x rows
__global__ void wtrans_kernel(const float* __restrict__ in, __nv_bfloat16* __restrict__ out,
                              int rows, int cols) {
    __shared__ float t[32][33];
    int r0 = blockIdx.y * 32, c0 = blockIdx.x * 32;
    int tx = threadIdx.x & 31, ty = threadIdx.x >> 5;
    #pragma unroll
    for (int i = ty; i < 32; i += 8)
        t[i][tx] = in[(size_t)(r0 + i) * cols + c0 + tx];
    __syncthreads();
    #pragma unroll
    for (int i = ty; i < 32; i += 8)
        out[(size_t)(c0 + i) * rows + r0 + tx] = __float2bfloat16(t[tx][i]);
}

// -------------------- v transpose (from uv bf16) --------------------
__global__ void vtrans_kernel() {
    __shared__ __nv_bfloat16 t[32][33];
    int z = blockIdx.z;
    int s0 = blockIdx.x * 32, e0 = blockIdx.y * 32;
    int tx = threadIdx.x & 31, ty = threadIdx.x >> 5;
    #pragma unroll
    for (int i = ty; i < 32; i += 8)
        t[i][tx] = g_uvb[(size_t)(z * SEQ + s0 + i) * PROJ + EXP + e0 + tx];
    __syncthreads();
    #pragma unroll
    for (int i = ty; i < 32; i += 8)
        g_vtb[((size_t)z * EXP + e0 + i) * SEQ + s0 + tx] = t[tx][i];
}

// -------------------- q,k from base --------------------
__global__ void qkgen_kernel(const float* __restrict__ gamma,
                             const float* __restrict__ beta) {
    int idx = blockIdx.x * blockDim.x + threadIdx.x;
    int j = idx & (SH - 1);
    int row = idx >> 7;
    float base = __bfloat162float(g_uvb[(size_t)row * PROJ + 2 * EXP + j]);
    g_qb[idx] = __float2bfloat16(base * gamma[j] + beta[j]);
    g_kb[idx] = __float2bfloat16(base * gamma[SH + j] + beta[SH + j]);
}

// -------------------- generic NT tensor-core GEMM, fused epilogues ------
// C[m][n] = sum_k A[m][k] * B[n][k]
enum { EPI_G1 = 0, EPI_ATT = 1, EPI_O = 2, EPI_OUT = 3 };

template <int EPI>
__global__ void __launch_bounds__(256) mmnt_kernel(
    const __nv_bfloat16* __restrict__ A, int lda, long long strideA,
    const __nv_bfloat16* __restrict__ Bm, int ldb, long long strideB,
    void* __restrict__ Cout, int ldc, long long strideC,
    int Ksz,
    const float* __restrict__ bias,
    const float* __restrict__ resid) {
    __shared__ alignas(16) __nv_bfloat16 sA[2][BM * LDSH];
    __shared__ alignas(16) __nv_bfloat16 sB[2][BN * LDSH];
    int z = blockIdx.z;
    const __nv_bfloat16* Ag = A + (long long)z * strideA + (long long)(blockIdx.y * BM) * lda;
    const __nv_bfloat16* Bg = Bm + (long long)z * strideB + (long long)(blockIdx.x * BN) * ldb;
    int t = threadIdx.x;
    int KT = Ksz / BK;

    auto load_tile = [&](int kt, int s) {
        #pragma unroll
        for (int i = 0; i < 2; i++) {
            int c = t + i * 256;
            int row = c >> 2, kc = (c & 3) << 3;
            cp16(&sA[s][row * LDSH + kc], Ag + (long long)row * lda + kt * BK + kc);
        }
        #pragma unroll
        for (int i = 0; i < 2; i++) {
            int c = t + i * 256;
            int row = c >> 2, kc = (c & 3) << 3;
            cp16(&sB[s][row * LDSH + kc], Bg + (long long)row * ldb + kt * BK + kc);
        }
        asm volatile("cp.async.commit_group;\n");
    };

    float acc[2][8][4];
    #pragma unroll
    for (int i = 0; i < 2; i++)
        #pragma unroll
        for (int j = 0; j < 8; j++)
            #pragma unroll
            for (int l = 0; l < 4; l++) acc[i][j][l] = 0.f;

    int warp = t >> 5, lane = t & 31;
    int wm = warp & 3, wn = warp >> 2;          // 4 (M) x 2 (N) warps
    int fr = lane >> 2, fc = (lane & 3) * 2;

    load_tile(0, 0);
    for (int kt = 0; kt < KT; kt++) {
        int s = kt & 1;
        asm volatile("cp.async.wait_group 0;\n");
        __syncthreads();
        if (kt + 1 < KT) load_tile(kt + 1, s ^ 1);
        #pragma unroll
        for (int ks = 0; ks < 2; ks++) {
            int k0 = ks * 16;
            uint32_t a[2][4], b[8][2];
            #pragma unroll
            for (int mt = 0; mt < 2; mt++) {
                const __nv_bfloat16* p = &sA[s][(wm * 32 + mt * 16 + fr) * LDSH + k0 + fc];
                a[mt][0] = *(const uint32_t*)p;
                a[mt][1] = *(const uint32_t*)(p + 8 * LDSH);
                a[mt][2] = *(const uint32_t*)(p + 8);
                a[mt][3] = *(const uint32_t*)(p + 8 * LDSH + 8);
            }
            #pragma unroll
            for (int nt = 0; nt < 8; nt++) {
                const __nv_bfloat16* p = &sB[s][(wn * 64 + nt * 8 + fr) * LDSH + k0 + fc];
                b[nt][0] = *(const uint32_t*)p;
                b[nt][1] = *(const uint32_t*)(p + 8);
            }
            #pragma unroll
            for (int mt = 0; mt < 2; mt++)
                #pragma unroll
                for (int nt = 0; nt < 8; nt++) mma16816(acc[mt][nt], a[mt], b[nt]);
        }
    }

    // epilogue
    int bm0 = blockIdx.y * BM + wm * 32;
    int bn0 = blockIdx.x * BN + wn * 64;
    #pragma unroll
    for (int mt = 0; mt < 2; mt++) {
        #pragma unroll
        for (int nt = 0; nt < 8; nt++) {
            #pragma unroll
            for (int half = 0; half < 2; half++) {
                int gm = bm0 + mt * 16 + fr + half * 8;
                int gn = bn0 + nt * 8 + fc;
                float v0 = acc[mt][nt][half * 2 + 0];
                float v1 = acc[mt][nt][half * 2 + 1];
                if (EPI == EPI_G1) {
                    float c0 = v0 + bias[gn], c1 = v1 + bias[gn + 1];
                    c0 = c0 / (1.f + expf(-c0));
                    c1 = c1 / (1.f + expf(-c1));
                    __nv_bfloat162 h2;
                    h2.x = __float2bfloat16(c0);
                    h2.y = __float2bfloat16(c1);
                    *(__nv_bfloat162*)((__nv_bfloat16*)Cout + (size_t)gm * ldc + gn) = h2;
                } else if (EPI == EPI_ATT) {
                    float c0 = v0 * (1.f / (float)SEQ) + g_f[gm - gn + (SEQ - 1)];
                    float c1 = v1 * (1.f / (float)SEQ) + g_f[gm - (gn + 1) + (SEQ - 1)];
                    c0 = fmaxf(c0, 0.f);
                    c1 = fmaxf(c1, 0.f);
                    __nv_bfloat16* cp = (__nv_bfloat16*)Cout + (long long)z * strideC;
                    __nv_bfloat162 h2;
                    h2.x = __float2bfloat16(c0 * c0);
                    h2.y = __float2bfloat16(c1 * c1);
                    *(__nv_bfloat162*)(cp + (size_t)gm * ldc + gn) = h2;
                } else if (EPI == EPI_O) {
                    float u0 = __bfloat162float(g_uvb[(size_t)(z * SEQ + gm) * PROJ + gn]);
                    float u1 = __bfloat162float(g_uvb[(size_t)(z * SEQ + gm) * PROJ + gn + 1]);
                    __nv_bfloat16* cp = (__nv_bfloat16*)Cout + (long long)z * strideC;
                    __nv_bfloat162 h2;
                    h2.x = __float2bfloat16(v0 * u0);
                    h2.y = __float2bfloat16(v1 * u1);
                    *(__nv_bfloat162*)(cp + (size_t)gm * ldc + gn) = h2;
                } else {  // EPI_OUT
                    float c0 = v0 + bias[gn] + resid[(size_t)gm * DIM + gn];
                    float c1 = v1 + bias[gn + 1] + resid[(size_t)gm * DIM + gn + 1];
                    float2 f2 = make_float2(c0, c1);
                    *(float2*)((float*)Cout + (size_t)gm * ldc + gn) = f2;
                }
            }
        }
    }
}

// -------------------- launch --------------------
extern "C" void kernel_launch(void* const* d_in, const int* in_sizes, int n_in,
                              void* d_out, int out_size) {
    const float* x          = (const float*)d_in[0];
    const float* W1         = (const float*)d_in[1];
    const float* b1         = (const float*)d_in[2];
    const float* W2         = (const float*)d_in[3];
    const float* b2         = (const float*)d_in[4];
    const float* rope_a     = (const float*)d_in[5];
    const float* rope_b     = (const float*)d_in[6];
    const float* gamma      = (const float*)d_in[7];
    const float* beta       = (const float*)d_in[8];
    const float* norm_scale = (const float*)d_in[9];
    float* out = (float*)d_out;

    void *p_xnb, *p_uvb, *p_w1t, *p_w2t, *p_qb, *p_kb, *p_attb, *p_vtb, *p_ob;
    cudaGetSymbolAddress(&p_xnb, g_xnb);
    cudaGetSymbolAddress(&p_uvb, g_uvb);
    cudaGetSymbolAddress(&p_w1t, g_w1t);
    cudaGetSymbolAddress(&p_w2t, g_w2t);
    cudaGetSymbolAddress(&p_qb, g_qb);
    cudaGetSymbolAddress(&p_kb, g_kb);
    cudaGetSymbolAddress(&p_attb, g_attb);
    cudaGetSymbolAddress(&p_vtb, g_vtb);
    cudaGetSymbolAddress(&p_ob, g_ob);

    rmsnorm_kernel <<<NROWS, 128>>>(x, norm_scale);
    toeplitz_kernel<<<SEQ / 256, 256>>>(rope_a, rope_b);
    wtrans_kernel  <<<dim3(PROJ / 32, DIM / 32), 256>>>(W1, (__nv_bfloat16*)p_w1t, DIM, PROJ);
    wtrans_kernel  <<<dim3(DIM / 32, EXP / 32), 256>>>(W2, (__nv_bfloat16*)p_w2t, EXP, DIM);

    // uv = swish(xn @ W1 + b1)
    mmnt_kernel<EPI_G1><<<dim3(PROJ / BN, NROWS / BM, 1), 256>>>(
        (const __nv_bfloat16*)p_xnb, DIM, 0,
        (const __nv_bfloat16*)p_w1t, DIM, 0,
        p_uvb, PROJ, 0, DIM, b1, nullptr);

    qkgen_kernel <<<NROWS * SH / 256, 256>>>(gamma, beta);
    vtrans_kernel<<<dim3(SEQ / 32, EXP / 32, BATCH), 256>>>();

    // att = relu(q@k^T/SEQ + f)^2
    mmnt_kernel<EPI_ATT><<<dim3(SEQ / BN, SEQ / BM, BATCH), 256>>>(
        (const __nv_bfloat16*)p_qb, SH, (long long)SEQ * SH,
        (const __nv_bfloat16*)p_kb, SH, (long long)SEQ * SH,
        p_attb, SEQ, (long long)SEQ * SEQ, SH, nullptr, nullptr);

    // o = u * (att @ v)   (B = v^T, NT form)
    mmnt_kernel<EPI_O><<<dim3(EXP / BN, SEQ / BM, BATCH), 256>>>(
        (const __nv_bfloat16*)p_attb, SEQ, (long long)SEQ * SEQ,
        (const __nv_bfloat16*)p_vtb, SEQ, (long long)EXP * SEQ,
        p_ob, EXP, (long long)SEQ * EXP, SEQ, nullptr, nullptr);

    // out = o @ W2 + b2 + x
    mmnt_kernel<EPI_OUT><<<dim3(DIM / BN, NROWS / BM, 1), 256>>>(
        (const __nv_bfloat16*)p_ob, EXP, 0,
        (const __nv_bfloat16*)p_w2t, EXP, 0,
        out, DIM, 0, EXP, b2, x);
}

// round 5
// speedup vs baseline: 7.4380x; 1.0922x over previous
#include <cuda_runtime.h>
#include <cuda_bf16.h>
#include <math.h>
#include <stdint.h>

#define BATCH 8
#define SEQ   2048
#define DIM   512
#define SH    128
#define EXP   1024
#define PROJ  2176
#define NROWS (BATCH * SEQ)

#define BMT 128
#define BKT 64
#define STAGES 4

// -------------------- scratch --------------------
__device__ alignas(16) __nv_bfloat16 g_xnb[NROWS * DIM];
__device__ alignas(16) __nv_bfloat16 g_uvb[(size_t)NROWS * PROJ];
__device__ alignas(16) __nv_bfloat16 g_w1t[(size_t)PROJ * DIM];
__device__ alignas(16) __nv_bfloat16 g_w2t[(size_t)DIM * EXP];
__device__ alignas(16) __nv_bfloat16 g_qb [NROWS * SH];
__device__ alignas(16) __nv_bfloat16 g_kb [NROWS * SH];
__device__ alignas(16) __nv_bfloat16 g_attb[(size_t)BATCH * SEQ * SEQ];
__device__ alignas(16) __nv_bfloat16 g_vtb [(size_t)BATCH * EXP * SEQ];
__device__ alignas(16) __nv_bfloat16 g_ob  [(size_t)NROWS * EXP];
__device__ float g_f[2 * SEQ - 1];

// -------------------- helpers --------------------
__device__ __forceinline__ uint32_t smem_u32(const void* p) {
    uint32_t a;
    asm("{ .reg .u64 t; cvta.to.shared.u64 t, %1; cvt.u32.u64 %0, t; }" : "=r"(a) : "l"(p));
    return a;
}
__device__ __forceinline__ void cp16s(uint32_t saddr, const void* g) {
    asm volatile("cp.async.cg.shared.global [%0], [%1], 16;\n" :: "r"(saddr), "l"(g));
}
#define CP_COMMIT() asm volatile("cp.async.commit_group;\n" ::: "memory")
#define SWZ(o) ((o) ^ (((o) >> 3) & 0x70))

__device__ __forceinline__ void mma16816(float* c, const uint32_t* a, const uint32_t* b) {
    asm volatile(
        "mma.sync.aligned.m16n8k16.row.col.f32.bf16.bf16.f32 "
        "{%0,%1,%2,%3},{%4,%5,%6,%7},{%8,%9},{%0,%1,%2,%3};\n"
        : "+f"(c[0]), "+f"(c[1]), "+f"(c[2]), "+f"(c[3])
        : "r"(a[0]), "r"(a[1]), "r"(a[2]), "r"(a[3]), "r"(b[0]), "r"(b[1]));
}
__device__ __forceinline__ void ldsm4(uint32_t* r, uint32_t addr) {
    asm volatile("ldmatrix.sync.aligned.m8n8.x4.shared.b16 {%0,%1,%2,%3}, [%4];"
        : "=r"(r[0]), "=r"(r[1]), "=r"(r[2]), "=r"(r[3]) : "r"(addr));
}

// -------------------- prep kernels --------------------
__global__ void rmsnorm_kernel(const float* __restrict__ x,
                               const float* __restrict__ ns_p) {
    int row = blockIdx.x;
    const float* xr = x + (size_t)row * DIM;
    __nv_bfloat16* outr = g_xnb + (size_t)row * DIM;
    float s = 0.f;
    for (int i = threadIdx.x; i < DIM; i += blockDim.x) { float v = xr[i]; s += v * v; }
    __shared__ float warp_s[4];
    #pragma unroll
    for (int off = 16; off > 0; off >>= 1) s += __shfl_down_sync(0xffffffffu, s, off);
    int lane = threadIdx.x & 31, wid = threadIdx.x >> 5;
    if (lane == 0) warp_s[wid] = s;
    __syncthreads();
    if (wid == 0) {
        float t = (lane < 4) ? warp_s[lane] : 0.f;
        #pragma unroll
        for (int off = 2; off > 0; off >>= 1) t += __shfl_down_sync(0xffffffffu, t, off);
        if (lane == 0) warp_s[0] = t;
    }
    __syncthreads();
    float scale = rsqrtf(warp_s[0] * (1.f / (float)DIM) + 1e-6f) * ns_p[0];
    for (int i = threadIdx.x; i < DIM; i += blockDim.x)
        outr[i] = __float2bfloat16(xr[i] * scale);
}

__global__ void toeplitz_kernel(const float* __restrict__ a,
                                const float* __restrict__ b) {
    __shared__ float sp[SEQ / 2];
    __shared__ float sr[SEQ / 2];
    for (int i = threadIdx.x; i < SEQ / 2; i += blockDim.x) {
        float a1 = a[i], a2 = a[i + SEQ / 2];
        float b1v = b[i], b2v = b[i + SEQ / 2];
        sp[i] = a1 * b1v + a2 * b2v;
        sr[i] = a2 * b1v - a1 * b2v;
    }
    __syncthreads();
    int d = blockIdx.x * blockDim.x + threadIdx.x;
    if (d >= SEQ) return;
    float sumc = 0.f, sums = 0.f;
    const float log1e4 = 9.210340371976184f;
    for (int i = 0; i < SEQ / 2; i++) {
        float theta = expf(-((float)i * (1.f / (SEQ / 2))) * log1e4);
        float s, c;
        sincosf((float)d * theta, &s, &c);
        sumc += sp[i] * c;
        sums += sr[i] * s;
    }
    g_f[(SEQ - 1) + d] = sumc - sums;
    g_f[(SEQ - 1) - d] = sumc + sums;
}

__global__ void wtrans_kernel(const float* __restrict__ in, __nv_bfloat16* __restrict__ out,
                              int rows, int cols) {
    __shared__ float t[32][33];
    int r0 = blockIdx.y * 32, c0 = blockIdx.x * 32;
    int tx = threadIdx.x & 31, ty = threadIdx.x >> 5;
    #pragma unroll
    for (int i = ty; i < 32; i += 8)
        t[i][tx] = in[(size_t)(r0 + i) * cols + c0 + tx];
    __syncthreads();
    #pragma unroll
    for (int i = ty; i < 32; i += 8)
        out[(size_t)(c0 + i) * rows + r0 + tx] = __float2bfloat16(t[tx][i]);
}

__global__ void vtrans_kernel() {
    __shared__ __nv_bfloat16 t[32][33];
    int z = blockIdx.z;
    int s0 = blockIdx.x * 32, e0 = blockIdx.y * 32;
    int tx = threadIdx.x & 31, ty = threadIdx.x >> 5;
    #pragma unroll
    for (int i = ty; i < 32; i += 8)
        t[i][tx] = g_uvb[(size_t)(z * SEQ + s0 + i) * PROJ + EXP + e0 + tx];
    __syncthreads();
    #pragma unroll
    for (int i = ty; i < 32; i += 8)
        g_vtb[((size_t)z * EXP + e0 + i) * SEQ + s0 + tx] = t[tx][i];
}

__global__ void qkgen_kernel(const float* __restrict__ gamma,
                             const float* __restrict__ beta) {
    int idx = blockIdx.x * blockDim.x + threadIdx.x;
    int j = idx & (SH - 1);
    int row = idx >> 7;
    float base = __bfloat162float(g_uvb[(size_t)row * PROJ + 2 * EXP + j]);
    g_qb[idx] = __float2bfloat16(base * gamma[j] + beta[j]);
    g_kb[idx] = __float2bfloat16(base * gamma[SH + j] + beta[SH + j]);
}

// -------------------- HMMA NT GEMM, ldmatrix + 4-stage pipeline --------------------
// C[m][n] = sum_k A[m][k]*B[n][k]
enum { EPI_G1 = 0, EPI_ATT = 1, EPI_O = 2, EPI_OUT = 3 };

template <int BN, int EPI>
__global__ void __launch_bounds__(256, 1) tc_gemm(
    const __nv_bfloat16* __restrict__ A, int lda, long long strideA,
    const __nv_bfloat16* __restrict__ Bm, int ldb, long long strideB,
    void* __restrict__ Cout, int ldc, long long strideC,
    int KT,
    const float* __restrict__ bias,
    const float* __restrict__ resid) {
    constexpr int NW_N = BN / 64;            // warps along N (64 n per warp)
    constexpr int NW_M = 8 / NW_N;           // warps along M
    constexpr int MT = BMT / (NW_M * 16);    // 16-row m-tiles per warp
    constexpr int A_BYTES = BMT * 128;       // 128 rows x 64 halves
    constexpr int B_BYTES = BN * 128;
    constexpr int STAGE_BYTES = A_BYTES + B_BYTES;

    extern __shared__ char smem[];
    uint32_t sb = (smem_u32(smem) + 1023) & ~1023u;
    int t = threadIdx.x;
    int warp = t >> 5, lane = t & 31;
    int wn = warp % NW_N, wm = warp / NW_N;
    int z = blockIdx.z;

    const __nv_bfloat16* Ag = A + (long long)z * strideA + (long long)(blockIdx.y * BMT) * lda;
    const __nv_bfloat16* Bg = Bm + (long long)z * strideB + (long long)(blockIdx.x * BN) * ldb;

    // ldmatrix per-lane relative offsets
    uint32_t a_off = (uint32_t)((wm * MT * 16 + (lane & 15)) * 128 + (lane & 16));
    uint32_t b_off = (uint32_t)((wn * 64 + (lane & 7) + ((lane >> 1) & 8)) * 128 + (lane & 8) * 2);

    auto load_tile = [&](int j) {
        int s = j % STAGES;
        uint32_t sA = sb + s * STAGE_BYTES;
        uint32_t sB = sA + A_BYTES;
        const __nv_bfloat16* Asrc = Ag + j * BKT;
        const __nv_bfloat16* Bsrc = Bg + j * BKT;
        #pragma unroll
        for (int i = 0; i < (BMT * 8) / 256; i++) {
            int c = t + i * 256;
            int row = c >> 3, kc = c & 7;
            cp16s(sA + SWZ(row * 128 + kc * 16), Asrc + (long long)row * lda + kc * 8);
        }
        #pragma unroll
        for (int i = 0; i < (BN * 8) / 256; i++) {
            int c = t + i * 256;
            int row = c >> 3, kc = c & 7;
            cp16s(sB + SWZ(row * 128 + kc * 16), Bsrc + (long long)row * ldb + kc * 8);
        }
        CP_COMMIT();
    };

    float acc[MT][8][4];
    #pragma unroll
    for (int i = 0; i < MT; i++)
        #pragma unroll
        for (int j = 0; j < 8; j++)
            #pragma unroll
            for (int l = 0; l < 4; l++) acc[i][j][l] = 0.f;

    #pragma unroll
    for (int j = 0; j < STAGES - 1; j++)
        if (j < KT) load_tile(j);

    for (int kt = 0; kt < KT; kt++) {
        int committed = (kt + STAGES - 1 < KT) ? (kt + STAGES - 1) : KT;
        int pend = committed - kt - 1;
        if (pend >= 2)      asm volatile("cp.async.wait_group 2;\n" ::: "memory");
        else if (pend == 1) asm volatile("cp.async.wait_group 1;\n" ::: "memory");
        else                asm volatile("cp.async.wait_group 0;\n" ::: "memory");
        __syncthreads();

        int j = kt + STAGES - 1;
        if (j < KT) load_tile(j);

        int s = kt % STAGES;
        uint32_t sA = sb + s * STAGE_BYTES;
        uint32_t sB = sA + A_BYTES;
        #pragma unroll
        for (int ks = 0; ks < 4; ks++) {
            uint32_t a[MT][4], b[8][2];
            #pragma unroll
            for (int mt = 0; mt < MT; mt++)
                ldsm4(a[mt], sA + SWZ(a_off + mt * 2048 + ks * 32));
            #pragma unroll
            for (int i = 0; i < 4; i++) {
                uint32_t r[4];
                ldsm4(r, sB + SWZ(b_off + i * 2048 + ks * 32));
                b[2 * i][0] = r[0]; b[2 * i][1] = r[1];
                b[2 * i + 1][0] = r[2]; b[2 * i + 1][1] = r[3];
            }
            #pragma unroll
            for (int mt = 0; mt < MT; mt++)
                #pragma unroll
                for (int nt = 0; nt < 8; nt++) mma16816(acc[mt][nt], a[mt], b[nt]);
        }
    }

    // -------- epilogue --------
    int fr = lane >> 2, fc = (lane & 3) * 2;
    int bm0 = blockIdx.y * BMT + wm * MT * 16;
    int bn0 = blockIdx.x * BN + wn * 64;
    #pragma unroll
    for (int mt = 0; mt < MT; mt++) {
        #pragma unroll
        for (int nt = 0; nt < 8; nt++) {
            #pragma unroll
            for (int half = 0; half < 2; half++) {
                int gm = bm0 + mt * 16 + fr + half * 8;
                int gn = bn0 + nt * 8 + fc;
                float v0 = acc[mt][nt][half * 2 + 0];
                float v1 = acc[mt][nt][half * 2 + 1];
                if (EPI == EPI_G1) {
                    float c0 = v0 + bias[gn], c1 = v1 + bias[gn + 1];
                    c0 = c0 / (1.f + expf(-c0));
                    c1 = c1 / (1.f + expf(-c1));
                    __nv_bfloat162 h2;
                    h2.x = __float2bfloat16(c0);
                    h2.y = __float2bfloat16(c1);
                    *(__nv_bfloat162*)((__nv_bfloat16*)Cout + (size_t)gm * ldc + gn) = h2;
                } else if (EPI == EPI_ATT) {
                    float c0 = v0 * (1.f / (float)SEQ) + g_f[gm - gn + (SEQ - 1)];
                    float c1 = v1 * (1.f / (float)SEQ) + g_f[gm - gn - 1 + (SEQ - 1)];
                    c0 = fmaxf(c0, 0.f);
                    c1 = fmaxf(c1, 0.f);
                    __nv_bfloat16* cp = (__nv_bfloat16*)Cout + (long long)z * strideC;
                    __nv_bfloat162 h2;
                    h2.x = __float2bfloat16(c0 * c0);
                    h2.y = __float2bfloat16(c1 * c1);
                    *(__nv_bfloat162*)(cp + (size_t)gm * ldc + gn) = h2;
                } else if (EPI == EPI_O) {
                    float u0 = __bfloat162float(g_uvb[(size_t)(z * SEQ + gm) * PROJ + gn]);
                    float u1 = __bfloat162float(g_uvb[(size_t)(z * SEQ + gm) * PROJ + gn + 1]);
                    __nv_bfloat16* cp = (__nv_bfloat16*)Cout + (long long)z * strideC;
                    __nv_bfloat162 h2;
                    h2.x = __float2bfloat16(v0 * u0);
                    h2.y = __float2bfloat16(v1 * u1);
                    *(__nv_bfloat162*)(cp + (size_t)gm * ldc + gn) = h2;
                } else {
                    float c0 = v0 + bias[gn] + resid[(size_t)gm * DIM + gn];
                    float c1 = v1 + bias[gn + 1] + resid[(size_t)gm * DIM + gn + 1];
                    float2 f2 = make_float2(c0, c1);
                    *(float2*)((float*)Cout + (size_t)gm * ldc + gn) = f2;
                }
            }
        }
    }
}

// -------------------- launch --------------------
extern "C" void kernel_launch(void* const* d_in, const int* in_sizes, int n_in,
                              void* d_out, int out_size) {
    const float* x          = (const float*)d_in[0];
    const float* W1         = (const float*)d_in[1];
    const float* b1         = (const float*)d_in[2];
    const float* W2         = (const float*)d_in[3];
    const float* b2         = (const float*)d_in[4];
    const float* rope_a     = (const float*)d_in[5];
    const float* rope_b     = (const float*)d_in[6];
    const float* gamma      = (const float*)d_in[7];
    const float* beta       = (const float*)d_in[8];
    const float* norm_scale = (const float*)d_in[9];
    float* out = (float*)d_out;

    void *p_xnb, *p_uvb, *p_w1t, *p_w2t, *p_qb, *p_kb, *p_attb, *p_vtb, *p_ob;
    cudaGetSymbolAddress(&p_xnb, g_xnb);
    cudaGetSymbolAddress(&p_uvb, g_uvb);
    cudaGetSymbolAddress(&p_w1t, g_w1t);
    cudaGetSymbolAddress(&p_w2t, g_w2t);
    cudaGetSymbolAddress(&p_qb, g_qb);
    cudaGetSymbolAddress(&p_kb, g_kb);
    cudaGetSymbolAddress(&p_attb, g_attb);
    cudaGetSymbolAddress(&p_vtb, g_vtb);
    cudaGetSymbolAddress(&p_ob, g_ob);

    constexpr int SM128 = 1024 + STAGES * (128 * 128 + 128 * 128);   // ~132KB
    constexpr int SM256 = 1024 + STAGES * (128 * 128 + 256 * 128);   // ~197KB
    cudaFuncSetAttribute(tc_gemm<128, EPI_G1>,  cudaFuncAttributeMaxDynamicSharedMemorySize, SM128);
    cudaFuncSetAttribute(tc_gemm<256, EPI_ATT>, cudaFuncAttributeMaxDynamicSharedMemorySize, SM256);
    cudaFuncSetAttribute(tc_gemm<256, EPI_O>,   cudaFuncAttributeMaxDynamicSharedMemorySize, SM256);
    cudaFuncSetAttribute(tc_gemm<256, EPI_OUT>, cudaFuncAttributeMaxDynamicSharedMemorySize, SM256);

    rmsnorm_kernel <<<NROWS, 128>>>(x, norm_scale);
    toeplitz_kernel<<<SEQ / 256, 256>>>(rope_a, rope_b);
    wtrans_kernel  <<<dim3(PROJ / 32, DIM / 32), 256>>>(W1, (__nv_bfloat16*)p_w1t, DIM, PROJ);
    wtrans_kernel  <<<dim3(DIM / 32, EXP / 32), 256>>>(W2, (__nv_bfloat16*)p_w2t, EXP, DIM);

    // uv = swish(xn @ W1 + b1)     M=16384 N=2176 K=512
    tc_gemm<128, EPI_G1><<<dim3(PROJ / 128, NROWS / BMT, 1), 256, SM128>>>(
        (const __nv_bfloat16*)p_xnb, DIM, 0,
        (const __nv_bfloat16*)p_w1t, DIM, 0,
        p_uvb, PROJ, 0, DIM / BKT, b1, nullptr);

    qkgen_kernel <<<NROWS * SH / 256, 256>>>(gamma, beta);
    vtrans_kernel<<<dim3(SEQ / 32, EXP / 32, BATCH), 256>>>();

    // att = relu(q@k^T/SEQ + f)^2  per batch M=N=2048 K=128
    tc_gemm<256, EPI_ATT><<<dim3(SEQ / 256, SEQ / BMT, BATCH), 256, SM256>>>(
        (const __nv_bfloat16*)p_qb, SH, (long long)SEQ * SH,
        (const __nv_bfloat16*)p_kb, SH, (long long)SEQ * SH,
        p_attb, SEQ, (long long)SEQ * SEQ, SH / BKT, nullptr, nullptr);

    // o = u * (att @ v)            per batch M=2048 N=1024 K=2048
    tc_gemm<256, EPI_O><<<dim3(EXP / 256, SEQ / BMT, BATCH), 256, SM256>>>(
        (const __nv_bfloat16*)p_attb, SEQ, (long long)SEQ * SEQ,
        (const __nv_bfloat16*)p_vtb, SEQ, (long long)EXP * SEQ,
        p_ob, EXP, (long long)SEQ * EXP, SEQ / BKT, nullptr, nullptr);

    // out = o @ W2 + b2 + x        M=16384 N=512 K=1024
    tc_gemm<256, EPI_OUT><<<dim3(DIM / 256, NROWS / BMT, 1), 256, SM256>>>(
        (const __nv_bfloat16*)p_ob, EXP, 0,
        (const __nv_bfloat16*)p_w2t, EXP, 0,
        out, DIM, 0, EXP / BKT, b2, x);
}